// round 14
// baseline (speedup 1.0000x reference)
#include <cuda_runtime.h>
#include <math.h>
#include <stdint.h>

#define NMAX 50000
#define EMAX 800000
#define LRV  1000

// ---------------- scratch (device globals) ----------------
__device__ __align__(16) float g_q[NMAX * 128];
__device__ __align__(16) float g_k[NMAX * 128];
__device__ __align__(16) float g_v[NMAX * 128];
__device__ __align__(16) float g_outpre[NMAX * 128];
__device__ __align__(16) float g_eraw[EMAX * 8];   // CSR-position order
__device__ __align__(16) float g_etan[EMAX * 8];   // CSR-position order
__device__ __align__(16) float g_lrtab[LRV * 64];
__device__ __align__(16) int   g_cnt[NMAX];
__device__ __align__(16) int   g_row[NMAX + 1];
__device__ __align__(16) int   g_next[NMAX];
__device__ __align__(16) int   g_csr_src[EMAX];
__device__ __align__(16) int   g_csr_eid[EMAX];
__device__ __align__(16) int   g_pos[EMAX];        // edge id -> CSR position

// ---------------- f32x2 packed helpers (sm_100+) ----------------
typedef unsigned long long ull;
__device__ __forceinline__ ull pk2(float lo, float hi) {
    ull r; asm("mov.b64 %0,{%1,%2};" : "=l"(r) : "f"(lo), "f"(hi)); return r;
}
__device__ __forceinline__ void upk2(ull v, float& lo, float& hi) {
    asm("mov.b64 {%0,%1},%2;" : "=f"(lo), "=f"(hi) : "l"(v));
}
__device__ __forceinline__ ull ffma2(ull a, ull b, ull c) {
    ull d; asm("fma.rn.f32x2 %0,%1,%2,%3;" : "=l"(d) : "l"(a), "l"(b), "l"(c)); return d;
}

// ---------------- bf16 split helpers ----------------
__device__ __forceinline__ uint32_t bf2(float hi_, float lo_) {
    uint32_t r; asm("cvt.rn.bf16x2.f32 %0,%1,%2;" : "=r"(r) : "f"(hi_), "f"(lo_)); return r;
}
__device__ __forceinline__ void mma_bf16(float* c, const uint32_t* a, const uint32_t* b) {
    asm volatile(
        "mma.sync.aligned.m16n8k16.row.col.f32.bf16.bf16.f32 "
        "{%0,%1,%2,%3},{%4,%5,%6,%7},{%8,%9},{%0,%1,%2,%3};"
        : "+f"(c[0]), "+f"(c[1]), "+f"(c[2]), "+f"(c[3])
        : "r"(a[0]), "r"(a[1]), "r"(a[2]), "r"(a[3]), "r"(b[0]), "r"(b[1]));
}

// ---------------- fused lrtab + hist ----------------
#define LRTAB_BLOCKS 125
__global__ __launch_bounds__(512) void lrtab_hist(const float* __restrict__ W1,
                                                  const float* __restrict__ b1,
                                                  const float* __restrict__ lr_emb,
                                                  const int* __restrict__ ei, int E) {
    int t = threadIdx.x;
    if (blockIdx.x < LRTAB_BLOCKS) {
        int id = blockIdx.x * 8 + (t >> 6);
        int j  = t & 63;
        float s = b1[j];
        const float* emb = lr_emb + (size_t)id * 32;
#pragma unroll
        for (int k = 0; k < 32; k++) s += W1[j * 38 + 6 + k] * emb[k];
        g_lrtab[(size_t)id * 64 + j] = s;
    } else {
        int e = (blockIdx.x - LRTAB_BLOCKS) * 512 + t;
        if (e < E) atomicAdd(&g_cnt[ei[E + e]], 1);
    }
}

__global__ __launch_bounds__(1024) void scan_kernel(int n) {
    __shared__ int wsum[32];
    int t    = threadIdx.x;
    int per  = (n + 1023) >> 10;
    int base = t * per;
    int sum = 0;
    for (int i = 0; i < per; i++) {
        int idx = base + i;
        if (idx < n) sum += g_cnt[idx];
    }
    int lane = t & 31, wid = t >> 5;
    int v = sum;
#pragma unroll
    for (int o = 1; o < 32; o <<= 1) {
        int u = __shfl_up_sync(0xffffffffu, v, o);
        if (lane >= o) v += u;
    }
    if (lane == 31) wsum[wid] = v;
    __syncthreads();
    if (wid == 0) {
        int w = wsum[lane];
#pragma unroll
        for (int o = 1; o < 32; o <<= 1) {
            int u = __shfl_up_sync(0xffffffffu, w, o);
            if (lane >= o) w += u;
        }
        wsum[lane] = w;
    }
    __syncthreads();
    int excl = v - sum + (wid > 0 ? wsum[wid - 1] : 0);
    int run = excl;
    for (int i = 0; i < per; i++) {
        int idx = base + i;
        if (idx < n) {
            g_row[idx]  = run;
            g_next[idx] = run;
            run += g_cnt[idx];
        }
    }
    if (t == 1023) g_row[n] = run;
}

__global__ void scatter_kernel(const int* __restrict__ ei, int E) {
    int e = blockIdx.x * blockDim.x + threadIdx.x;
    if (e >= E) return;
    int dst = ei[E + e];
    int pos = atomicAdd(&g_next[dst], 1);
    g_csr_src[pos] = ei[e];
    g_csr_eid[pos] = e;
    g_pos[e] = pos;
}

// ---------------- bf16-split tensor-core GEMM (unchanged) ----------------
#define SW 9
__device__ __forceinline__ void gemm_bf16_core(const float* __restrict__ A, int nrows,
                                               const float* __restrict__ W,
                                               const float* __restrict__ bias,
                                               float* __restrict__ C) {
    __shared__ uint32_t sAhi[128 * SW], sAlo[128 * SW];
    __shared__ uint32_t sWhi[128 * SW], sWlo[128 * SW];

    int t    = threadIdx.x;
    int row0 = blockIdx.x * 128;
    int wid  = t >> 5;
    int lane = t & 31;
    int gid  = lane >> 2;
    int tig  = lane & 3;
    int wm   = wid & 3;
    int wn   = wid >> 2;

    float c[2][8][4];
#pragma unroll
    for (int m = 0; m < 2; m++)
#pragma unroll
        for (int nf = 0; nf < 8; nf++)
#pragma unroll
            for (int i = 0; i < 4; i++) c[m][nf][i] = 0.0f;

    int sr = t >> 1;
    int sk = (t & 1) * 8;
    int sw0 = sk >> 1;

    for (int k0 = 0; k0 < 128; k0 += 16) {
        {
            float4 v0 = make_float4(0.f, 0.f, 0.f, 0.f), v1 = v0;
            if (row0 + sr < nrows) {
                const float* ap = A + (size_t)(row0 + sr) * 128 + k0 + sk;
                v0 = *(const float4*)ap;
                v1 = *(const float4*)(ap + 4);
            }
            float vs[8] = {v0.x, v0.y, v0.z, v0.w, v1.x, v1.y, v1.z, v1.w};
#pragma unroll
            for (int j = 0; j < 4; j++) {
                float x0 = vs[2 * j], x1 = vs[2 * j + 1];
                uint32_t h = bf2(x1, x0);
                float h0 = __uint_as_float(h << 16);
                float h1 = __uint_as_float(h & 0xffff0000u);
                uint32_t l = bf2(x1 - h1, x0 - h0);
                sAhi[sr * SW + sw0 + j] = h;
                sAlo[sr * SW + sw0 + j] = l;
            }
        }
        {
            const float* wp = W + (size_t)sr * 128 + k0 + sk;
            float4 v0 = *(const float4*)wp;
            float4 v1 = *(const float4*)(wp + 4);
            float vs[8] = {v0.x, v0.y, v0.z, v0.w, v1.x, v1.y, v1.z, v1.w};
#pragma unroll
            for (int j = 0; j < 4; j++) {
                float x0 = vs[2 * j], x1 = vs[2 * j + 1];
                uint32_t h = bf2(x1, x0);
                float h0 = __uint_as_float(h << 16);
                float h1 = __uint_as_float(h & 0xffff0000u);
                uint32_t l = bf2(x1 - h1, x0 - h0);
                sWhi[sr * SW + sw0 + j] = h;
                sWlo[sr * SW + sw0 + j] = l;
            }
        }
        __syncthreads();

        uint32_t bhi[8][2], blo[8][2];
#pragma unroll
        for (int nf = 0; nf < 8; nf++) {
            int n = wn * 64 + nf * 8 + gid;
            bhi[nf][0] = sWhi[n * SW + tig];
            bhi[nf][1] = sWhi[n * SW + 4 + tig];
            blo[nf][0] = sWlo[n * SW + tig];
            blo[nf][1] = sWlo[n * SW + 4 + tig];
        }
#pragma unroll
        for (int m = 0; m < 2; m++) {
            int r = wm * 32 + m * 16 + gid;
            uint32_t ahi[4], alo[4];
            ahi[0] = sAhi[r * SW + tig];
            ahi[1] = sAhi[(r + 8) * SW + tig];
            ahi[2] = sAhi[r * SW + 4 + tig];
            ahi[3] = sAhi[(r + 8) * SW + 4 + tig];
            alo[0] = sAlo[r * SW + tig];
            alo[1] = sAlo[(r + 8) * SW + tig];
            alo[2] = sAlo[r * SW + 4 + tig];
            alo[3] = sAlo[(r + 8) * SW + 4 + tig];
#pragma unroll
            for (int nf = 0; nf < 8; nf++) {
                mma_bf16(c[m][nf], ahi, bhi[nf]);
                mma_bf16(c[m][nf], ahi, blo[nf]);
                mma_bf16(c[m][nf], alo, bhi[nf]);
            }
        }
        __syncthreads();
    }

#pragma unroll
    for (int nf = 0; nf < 8; nf++) {
        int col = wn * 64 + nf * 8 + 2 * tig;
        float b0 = bias ? bias[col] : 0.0f;
        float b1 = bias ? bias[col + 1] : 0.0f;
#pragma unroll
        for (int m = 0; m < 2; m++) {
            int r = row0 + wm * 32 + m * 16 + gid;
            if (r < nrows)
                *(float2*)(C + (size_t)r * 128 + col) =
                    make_float2(c[m][nf][0] + b0, c[m][nf][1] + b1);
            if (r + 8 < nrows)
                *(float2*)(C + (size_t)(r + 8) * 128 + col) =
                    make_float2(c[m][nf][2] + b0, c[m][nf][3] + b1);
        }
    }
}

__global__ __launch_bounds__(256) void gemm_tc_qkv(const float* __restrict__ A, int nrows,
                                                   const float* __restrict__ Wq,
                                                   const float* __restrict__ Wk,
                                                   const float* __restrict__ Wv) {
    const float* W = (blockIdx.y == 0) ? Wq : (blockIdx.y == 1) ? Wk : Wv;
    float* C       = (blockIdx.y == 0) ? g_q : (blockIdx.y == 1) ? g_k : g_v;
    gemm_bf16_core(A, nrows, W, nullptr, C);
}

__global__ __launch_bounds__(256) void gemm_tc_proj(const float* __restrict__ A, int nrows,
                                                    const float* __restrict__ W,
                                                    const float* __restrict__ bias,
                                                    float* __restrict__ C) {
    gemm_bf16_core(A, nrows, W, bias, C);
}

// ---------------- MLP kernel: LANE-QUAD per edge (quarter registers -> occupancy) ----
// Lanes (4r..4r+3) handle edge ebase+r; q4 = lane&3 owns j-quarter [q4*16, q4*16+16).
// Each lane accumulates heads {q4*2, q4*2+1}. Writes bias to g_eraw[pos] (float2).
#define TSTR 68  // staging row stride (floats)
__global__ __launch_bounds__(128, 7) void mlp_kernel(
    const float* __restrict__ ea,
    const float* __restrict__ W1, const float* __restrict__ W2,
    const float* __restrict__ b2, const float* __restrict__ wb,
    const float* __restrict__ p_sigma, const int* __restrict__ p_log1p,
    const float* __restrict__ p_cscale, int E) {
    // quarter-padded packed weights (strides chosen for 16B-aligned ulonglong2 loads)
    __shared__ __align__(16) ull sW1p4[6 * 40];    // [c][q4*10 + jj], jj<8
    __shared__ __align__(16) ull sW2p4[32 * 40];   // [i][q4*10 + m],  m<8
    __shared__ ull   sWbp2[8 * 18];                // [h][i2]
    __shared__ float sb2[32];
    __shared__ float sTab[4][8 * TSTR];            // per-warp staging of 8 lrtab rows

    int t    = threadIdx.x;
    int wid  = t >> 5;
    int lane = t & 31;
    int q4   = lane & 3;
    int erow = lane >> 2;          // 0..7

    for (int i = t; i < 6 * 32; i += 128) {
        int c = i >> 5, j2 = i & 31;             // j2 = j pair index 0..31
        sW1p4[c * 40 + (j2 >> 3) * 10 + (j2 & 7)] =
            pk2(W1[(2 * j2) * 38 + c], W1[(2 * j2 + 1) * 38 + c]);
    }
    for (int i = t; i < 32 * 32; i += 128) {
        int r = i >> 5, j2 = i & 31;
        sW2p4[r * 40 + (j2 >> 3) * 10 + (j2 & 7)] =
            pk2(W2[r * 64 + 2 * j2], W2[r * 64 + 2 * j2 + 1]);
    }
    for (int i = t; i < 8 * 16; i += 128) {
        int h = i >> 4, i2 = i & 15;
        sWbp2[h * 18 + i2] = pk2(wb[h * 32 + 2 * i2], wb[h * 32 + 2 * i2 + 1]);
    }
    if (t < 32) sb2[t] = b2[t];
    __syncthreads();

    float sigma  = fmaxf(p_sigma[0], 1e-6f);
    bool  ulog   = (p_log1p[0] != 0);
    float inv_cs = 1.0f / fmaxf(p_cscale[0], 1e-6f);

    int warpsTotal = gridDim.x * 4;
    for (int ebase = (blockIdx.x * 4 + wid) * 8; ebase < E; ebase += warpsTotal * 8) {
        int  e     = ebase + erow;
        bool valid = (e < E);

        // all 4 quad-lanes compute the same edge's cv (broadcast LDG, no shfl needed)
        float cv[6] = {0, 0, 0, 0, 0, 0};
        int   lr = 0;
        if (valid) {
            const float* a = ea + (size_t)e * 7;
            cv[0] = expf(-a[0] / sigma);
            cv[1] = ulog ? log1pf(fmaxf(a[1], 0.0f)) * inv_cs : a[1] * inv_cs;
            lr    = (int)a[2];
            cv[2] = fminf(fmaxf(a[3], 0.0f), 1.0f);
            cv[3] = fminf(fmaxf(a[4], 0.0f), 1.0f);
            cv[4] = fminf(fmaxf(a[5], 0.0f), 1.0f);
            cv[5] = fminf(fmaxf(a[6], 0.0f), 1.0f);
        }

        // stage 8 rows: 2 rows per iteration (16 lanes each, coalesced 256B)
        __syncwarp();
#pragma unroll
        for (int it2 = 0; it2 < 4; it2++) {
            int r     = it2 * 2 + (lane >> 4);
            int lrr   = __shfl_sync(0xffffffffu, lr, r * 4);  // lane with erow==r, q4==0
            int chunk = lane & 15;
            if (ebase + r < E) {
                float4 v = *(const float4*)(g_lrtab + (size_t)lrr * 64 + chunk * 4);
                *(float4*)&sTab[wid][r * TSTR + chunk * 4] = v;
            }
        }
        __syncwarp();

        // ---- layer 1: own j-quarter, h1 packed as 8 pairs ----
        ull cv2[6];
#pragma unroll
        for (int c = 0; c < 6; c++) cv2[c] = pk2(cv[c], cv[c]);

        const float* myrow = &sTab[wid][erow * TSTR + q4 * 16];
        ull h1p[8];
#pragma unroll
        for (int m = 0; m < 4; m++) {
            float4 v = ((const float4*)myrow)[m];
            h1p[2 * m]     = pk2(v.x, v.y);
            h1p[2 * m + 1] = pk2(v.z, v.w);
        }
#pragma unroll
        for (int jj = 0; jj < 8; jj++) {
            ull h = h1p[jj];
#pragma unroll
            for (int c = 0; c < 6; c++)
                h = ffma2(sW1p4[c * 40 + q4 * 10 + jj], cv2[c], h);
            float lo, hi;
            upk2(h, lo, hi);
            h1p[jj] = pk2(fmaxf(lo, 0.0f), fmaxf(hi, 0.0f));
        }

        // ---- layer 2 + 3: per i-pair, combine quarters via 2 shfls, accumulate bias --
        ull bias2[2] = {0, 0};
#pragma unroll 4
        for (int i2 = 0; i2 < 16; i2++) {
            const ulonglong2* wa  = (const ulonglong2*)&sW2p4[(2 * i2) * 40 + q4 * 10];
            const ulonglong2* wbq = (const ulonglong2*)&sW2p4[(2 * i2 + 1) * 40 + q4 * 10];
            ull accA = 0, accB = 0;
#pragma unroll
            for (int m = 0; m < 4; m++) {
                ulonglong2 wA = wa[m];
                accA = ffma2(h1p[2 * m], wA.x, accA);
                accA = ffma2(h1p[2 * m + 1], wA.y, accA);
                ulonglong2 wB = wbq[m];
                accB = ffma2(h1p[2 * m], wB.x, accB);
                accB = ffma2(h1p[2 * m + 1], wB.y, accB);
            }
            float aL, aH, bL, bH;
            upk2(accA, aL, aH);
            upk2(accB, bL, bH);
            float pA = aL + aH, pB = bL + bH;
            pA += __shfl_xor_sync(0xffffffffu, pA, 1);
            pB += __shfl_xor_sync(0xffffffffu, pB, 1);
            pA += __shfl_xor_sync(0xffffffffu, pA, 2);
            pB += __shfl_xor_sync(0xffffffffu, pB, 2);
            float sA = fmaxf(pA + sb2[2 * i2], 0.0f);
            float sB = fmaxf(pB + sb2[2 * i2 + 1], 0.0f);
            ull sp = pk2(sA, sB);
            bias2[0] = ffma2(sWbp2[(q4 * 2 + 0) * 18 + i2], sp, bias2[0]);
            bias2[1] = ffma2(sWbp2[(q4 * 2 + 1) * 18 + i2], sp, bias2[1]);
        }

        if (valid) {
            int pos = g_pos[e];
            float l0, h0, l1, h1;
            upk2(bias2[0], l0, h0);
            upk2(bias2[1], l1, h1);
            *(float2*)(g_eraw + (size_t)pos * 8 + q4 * 2) =
                make_float2(l0 + h0, l1 + h1);
        }
    }
}

// ---------------- dot kernel: warp per node; e_raw[pos] += (q.k)*dscale; 4x unroll ----
__global__ __launch_bounds__(256) void dot_kernel(const float* __restrict__ p_temp, int n) {
    int lane = threadIdx.x & 31;
    int node = (blockIdx.x * blockDim.x + threadIdx.x) >> 5;
    if (node >= n) return;
    int beg = g_row[node], end = g_row[node + 1];
    if (beg == end) return;

    float tau    = fmaxf(p_temp[0], 1e-6f);
    float dscale = 1.0f / (4.0f * tau);  // sqrt(DK)=4

    float4 qv = *(const float4*)(g_q + (size_t)node * 128 + lane * 4);

    bool storer = ((lane & 3) == 0);
    int  hidx   = lane >> 2;

    int i = beg;
    for (; i + 4 <= end; i += 4) {
        int s0 = g_csr_src[i];
        int s1 = g_csr_src[i + 1];
        int s2 = g_csr_src[i + 2];
        int s3 = g_csr_src[i + 3];
        float4 k0 = *(const float4*)(g_k + (size_t)s0 * 128 + lane * 4);
        float4 k1 = *(const float4*)(g_k + (size_t)s1 * 128 + lane * 4);
        float4 k2 = *(const float4*)(g_k + (size_t)s2 * 128 + lane * 4);
        float4 k3 = *(const float4*)(g_k + (size_t)s3 * 128 + lane * 4);
        float p0 = qv.x * k0.x + qv.y * k0.y + qv.z * k0.z + qv.w * k0.w;
        float p1 = qv.x * k1.x + qv.y * k1.y + qv.z * k1.z + qv.w * k1.w;
        float p2 = qv.x * k2.x + qv.y * k2.y + qv.z * k2.z + qv.w * k2.w;
        float p3 = qv.x * k3.x + qv.y * k3.y + qv.z * k3.z + qv.w * k3.w;
        p0 += __shfl_xor_sync(0xffffffffu, p0, 1);
        p1 += __shfl_xor_sync(0xffffffffu, p1, 1);
        p2 += __shfl_xor_sync(0xffffffffu, p2, 1);
        p3 += __shfl_xor_sync(0xffffffffu, p3, 1);
        p0 += __shfl_xor_sync(0xffffffffu, p0, 2);
        p1 += __shfl_xor_sync(0xffffffffu, p1, 2);
        p2 += __shfl_xor_sync(0xffffffffu, p2, 2);
        p3 += __shfl_xor_sync(0xffffffffu, p3, 2);
        if (storer) {
            float* d0 = g_eraw + (size_t)(i + 0) * 8 + hidx;
            float* d1 = g_eraw + (size_t)(i + 1) * 8 + hidx;
            float* d2 = g_eraw + (size_t)(i + 2) * 8 + hidx;
            float* d3 = g_eraw + (size_t)(i + 3) * 8 + hidx;
            *d0 = *d0 + p0 * dscale;
            *d1 = *d1 + p1 * dscale;
            *d2 = *d2 + p2 * dscale;
            *d3 = *d3 + p3 * dscale;
        }
    }
    for (; i < end; i++) {
        int src = g_csr_src[i];
        float4 kv = *(const float4*)(g_k + (size_t)src * 128 + lane * 4);
        float p = qv.x * kv.x + qv.y * kv.y + qv.z * kv.z + qv.w * kv.w;
        p += __shfl_xor_sync(0xffffffffu, p, 1);
        p += __shfl_xor_sync(0xffffffffu, p, 2);
        if (storer) {
            float* dst = g_eraw + (size_t)i * 8 + hidx;
            *dst = *dst + p * dscale;
        }
    }
}

// ---------------- node_attn: stats + tanh + e_out scatter + softmax + alpha.v ----------------
__global__ __launch_bounds__(256) void node_attn(float* __restrict__ e_out, int n) {
    int lane = threadIdx.x & 31;
    int node = (blockIdx.x * blockDim.x + threadIdx.x) >> 5;
    if (node >= n) return;
    int beg = g_row[node], end = g_row[node + 1];

    if (beg == end) {
        *(float4*)(g_outpre + (size_t)node * 128 + lane * 4) =
            make_float4(0.f, 0.f, 0.f, 0.f);
        return;
    }

    int head = lane & 7, sub = lane >> 3;

    float s1 = 0.0f, s2 = 0.0f;
    for (int i = beg + sub; i < end; i += 4) {
        float v = g_eraw[(size_t)i * 8 + head];
        s1 += v;
        s2 += v * v;
    }
    s1 += __shfl_xor_sync(0xffffffffu, s1, 8);
    s1 += __shfl_xor_sync(0xffffffffu, s1, 16);
    s2 += __shfl_xor_sync(0xffffffffu, s2, 8);
    s2 += __shfl_xor_sync(0xffffffffu, s2, 16);
    float c    = fmaxf((float)(end - beg), 1.0f);
    float m    = s1 / c;
    float var  = fmaxf(s2 / c - m * m, 0.0f);
    float rstd = 1.0f / (sqrtf(var + 1e-6f) + 1e-6f);

    float dn = 0.0f;
    for (int i = beg + sub; i < end; i += 4) {
        float v  = g_eraw[(size_t)i * 8 + head];
        float te = tanhf((v - m) * rstd);
        g_etan[(size_t)i * 8 + head] = te;
        int eid = g_csr_eid[i];
        e_out[(size_t)eid * 8 + head] = te;
        dn += expf(te);
    }
    dn += __shfl_xor_sync(0xffffffffu, dn, 8);
    dn += __shfl_xor_sync(0xffffffffu, dn, 16);
    float inv  = 1.0f / (dn + 1e-12f);
    float invh = __shfl_sync(0xffffffffu, inv, lane >> 2);
    int   hidx = lane >> 2;

    float4 acc = make_float4(0.f, 0.f, 0.f, 0.f);
    int i = beg;
    for (; i + 2 <= end; i += 2) {
        int s0 = g_csr_src[i];
        int s1i = g_csr_src[i + 1];
        float t0 = g_etan[(size_t)(i + 0) * 8 + hidx];
        float t1 = g_etan[(size_t)(i + 1) * 8 + hidx];
        float4 v0 = *(const float4*)(g_v + (size_t)s0 * 128 + lane * 4);
        float4 v1 = *(const float4*)(g_v + (size_t)s1i * 128 + lane * 4);
        float a0 = expf(t0) * invh;
        float a1 = expf(t1) * invh;
        acc.x += a0 * v0.x + a1 * v1.x;
        acc.y += a0 * v0.y + a1 * v1.y;
        acc.z += a0 * v0.z + a1 * v1.z;
        acc.w += a0 * v0.w + a1 * v1.w;
    }
    for (; i < end; i++) {
        int src = g_csr_src[i];
        float te    = g_etan[(size_t)i * 8 + hidx];
        float alpha = expf(te) * invh;
        float4 vv = *(const float4*)(g_v + (size_t)src * 128 + lane * 4);
        acc.x += alpha * vv.x;
        acc.y += alpha * vv.y;
        acc.z += alpha * vv.z;
        acc.w += alpha * vv.w;
    }
    *(float4*)(g_outpre + (size_t)node * 128 + lane * 4) = acc;
}

// ---------------- launch ----------------
extern "C" void kernel_launch(void* const* d_in, const int* in_sizes, int n_in,
                              void* d_out, int out_size) {
    const float* x   = (const float*)d_in[0];
    const int*   ei  = (const int*)d_in[1];
    const float* ea  = (const float*)d_in[2];
    const float* Wq  = (const float*)d_in[3];
    const float* Wk  = (const float*)d_in[4];
    const float* Wv  = (const float*)d_in[5];
    const float* lre = (const float*)d_in[6];
    const float* W1  = (const float*)d_in[7];
    const float* b1  = (const float*)d_in[8];
    const float* W2  = (const float*)d_in[9];
    const float* b2  = (const float*)d_in[10];
    const float* wb  = (const float*)d_in[11];
    const float* Wp  = (const float*)d_in[12];
    const float* bp  = (const float*)d_in[13];
    const float* p_sigma  = (const float*)d_in[14];
    const int*   p_log1p  = (const int*)d_in[15];
    const float* p_cscale = (const float*)d_in[16];
    const float* p_temp   = (const float*)d_in[17];

    int n = in_sizes[0] / 128;
    int E = in_sizes[1] / 2;

    float* out   = (float*)d_out;
    float* e_out = out + (size_t)n * 128;  // output layout: (out[N,128], e[E,8])

    void* pcnt;
    void* pop;
    cudaGetSymbolAddress(&pcnt, g_cnt);
    cudaGetSymbolAddress(&pop, g_outpre);

    // launch order matters for ncu's fixed capture slot (5th launch incl. memset)
    cudaMemsetAsync(pcnt, 0, (size_t)n * sizeof(int));                       // 1
    lrtab_hist<<<LRTAB_BLOCKS + (E + 511) / 512, 512>>>(W1, b1, lre, ei, E); // 2
    scan_kernel<<<1, 1024>>>(n);                                             // 3
    scatter_kernel<<<(E + 511) / 512, 512>>>(ei, E);                         // 4
    mlp_kernel<<<2048, 128>>>(ea, W1, W2, b2, wb, p_sigma, p_log1p,
                              p_cscale, E);                                  // 5 <- captured

    dim3 gq((n + 127) / 128, 3);
    gemm_tc_qkv<<<gq, 256>>>(x, n, Wq, Wk, Wv);

    dot_kernel<<<(n * 32 + 255) / 256, 256>>>(p_temp, n);

    node_attn<<<(n * 32 + 255) / 256, 256>>>(e_out, n);

    gemm_tc_proj<<<(n + 127) / 128, 256>>>((const float*)pop, n, Wp, bp, out);
}

// round 17
// speedup vs baseline: 1.2132x; 1.2132x over previous
#include <cuda_runtime.h>
#include <math.h>
#include <stdint.h>

#define NMAX 50000
#define EMAX 800000
#define LRV  1000

// ---------------- scratch (device globals) ----------------
__device__ __align__(16) float g_q[NMAX * 128];
__device__ __align__(16) float g_k[NMAX * 128];
__device__ __align__(16) float g_v[NMAX * 128];
__device__ __align__(16) float g_outpre[NMAX * 128];
__device__ __align__(16) float g_eraw[EMAX * 8];   // CSR-position order
__device__ __align__(16) float g_etan[EMAX * 8];   // CSR-position order
__device__ __align__(16) float g_lrtab[LRV * 64];
__device__ __align__(16) int   g_cnt[NMAX];
__device__ __align__(16) int   g_row[NMAX + 1];
__device__ __align__(16) int   g_next[NMAX];
__device__ __align__(16) int   g_csr_src[EMAX];
__device__ __align__(16) int   g_csr_eid[EMAX];
__device__ __align__(16) int   g_pos[EMAX];        // edge id -> CSR position

// ---------------- f32x2 packed helpers (sm_100+) ----------------
typedef unsigned long long ull;
__device__ __forceinline__ ull pk2(float lo, float hi) {
    ull r; asm("mov.b64 %0,{%1,%2};" : "=l"(r) : "f"(lo), "f"(hi)); return r;
}
__device__ __forceinline__ void upk2(ull v, float& lo, float& hi) {
    asm("mov.b64 {%0,%1},%2;" : "=f"(lo), "=f"(hi) : "l"(v));
}
__device__ __forceinline__ ull ffma2(ull a, ull b, ull c) {
    ull d; asm("fma.rn.f32x2 %0,%1,%2,%3;" : "=l"(d) : "l"(a), "l"(b), "l"(c)); return d;
}

// ---------------- bf16 split helpers ----------------
__device__ __forceinline__ uint32_t bf2(float hi_, float lo_) {
    uint32_t r; asm("cvt.rn.bf16x2.f32 %0,%1,%2;" : "=r"(r) : "f"(hi_), "f"(lo_)); return r;
}
__device__ __forceinline__ void mma_bf16(float* c, const uint32_t* a, const uint32_t* b) {
    asm volatile(
        "mma.sync.aligned.m16n8k16.row.col.f32.bf16.bf16.f32 "
        "{%0,%1,%2,%3},{%4,%5,%6,%7},{%8,%9},{%0,%1,%2,%3};"
        : "+f"(c[0]), "+f"(c[1]), "+f"(c[2]), "+f"(c[3])
        : "r"(a[0]), "r"(a[1]), "r"(a[2]), "r"(a[3]), "r"(b[0]), "r"(b[1]));
}

// ---------------- fused lrtab + hist ----------------
#define LRTAB_BLOCKS 125
__global__ __launch_bounds__(512) void lrtab_hist(const float* __restrict__ W1,
                                                  const float* __restrict__ b1,
                                                  const float* __restrict__ lr_emb,
                                                  const int* __restrict__ ei, int E) {
    int t = threadIdx.x;
    if (blockIdx.x < LRTAB_BLOCKS) {
        int id = blockIdx.x * 8 + (t >> 6);
        int j  = t & 63;
        float s = b1[j];
        const float* emb = lr_emb + (size_t)id * 32;
#pragma unroll
        for (int k = 0; k < 32; k++) s += W1[j * 38 + 6 + k] * emb[k];
        g_lrtab[(size_t)id * 64 + j] = s;
    } else {
        int e = (blockIdx.x - LRTAB_BLOCKS) * 512 + t;
        if (e < E) atomicAdd(&g_cnt[ei[E + e]], 1);
    }
}

__global__ __launch_bounds__(1024) void scan_kernel(int n) {
    __shared__ int wsum[32];
    int t    = threadIdx.x;
    int per  = (n + 1023) >> 10;
    int base = t * per;
    int sum = 0;
    for (int i = 0; i < per; i++) {
        int idx = base + i;
        if (idx < n) sum += g_cnt[idx];
    }
    int lane = t & 31, wid = t >> 5;
    int v = sum;
#pragma unroll
    for (int o = 1; o < 32; o <<= 1) {
        int u = __shfl_up_sync(0xffffffffu, v, o);
        if (lane >= o) v += u;
    }
    if (lane == 31) wsum[wid] = v;
    __syncthreads();
    if (wid == 0) {
        int w = wsum[lane];
#pragma unroll
        for (int o = 1; o < 32; o <<= 1) {
            int u = __shfl_up_sync(0xffffffffu, w, o);
            if (lane >= o) w += u;
        }
        wsum[lane] = w;
    }
    __syncthreads();
    int excl = v - sum + (wid > 0 ? wsum[wid - 1] : 0);
    int run = excl;
    for (int i = 0; i < per; i++) {
        int idx = base + i;
        if (idx < n) {
            g_row[idx]  = run;
            g_next[idx] = run;
            run += g_cnt[idx];
        }
    }
    if (t == 1023) g_row[n] = run;
}

__global__ void scatter_kernel(const int* __restrict__ ei, int E) {
    int e = blockIdx.x * blockDim.x + threadIdx.x;
    if (e >= E) return;
    int dst = ei[E + e];
    int pos = atomicAdd(&g_next[dst], 1);
    g_csr_src[pos] = ei[e];
    g_csr_eid[pos] = e;
    g_pos[e] = pos;
}

// ---------------- bf16-split tensor-core GEMM ----------------
#define SW 9
__device__ __forceinline__ void gemm_bf16_core(const float* __restrict__ A, int nrows,
                                               const float* __restrict__ W,
                                               const float* __restrict__ bias,
                                               float* __restrict__ C) {
    __shared__ uint32_t sAhi[128 * SW], sAlo[128 * SW];
    __shared__ uint32_t sWhi[128 * SW], sWlo[128 * SW];

    int t    = threadIdx.x;
    int row0 = blockIdx.x * 128;
    int wid  = t >> 5;
    int lane = t & 31;
    int gid  = lane >> 2;
    int tig  = lane & 3;
    int wm   = wid & 3;
    int wn   = wid >> 2;

    float c[2][8][4];
#pragma unroll
    for (int m = 0; m < 2; m++)
#pragma unroll
        for (int nf = 0; nf < 8; nf++)
#pragma unroll
            for (int i = 0; i < 4; i++) c[m][nf][i] = 0.0f;

    int sr = t >> 1;
    int sk = (t & 1) * 8;
    int sw0 = sk >> 1;

    for (int k0 = 0; k0 < 128; k0 += 16) {
        {
            float4 v0 = make_float4(0.f, 0.f, 0.f, 0.f), v1 = v0;
            if (row0 + sr < nrows) {
                const float* ap = A + (size_t)(row0 + sr) * 128 + k0 + sk;
                v0 = *(const float4*)ap;
                v1 = *(const float4*)(ap + 4);
            }
            float vs[8] = {v0.x, v0.y, v0.z, v0.w, v1.x, v1.y, v1.z, v1.w};
#pragma unroll
            for (int j = 0; j < 4; j++) {
                float x0 = vs[2 * j], x1 = vs[2 * j + 1];
                uint32_t h = bf2(x1, x0);
                float h0 = __uint_as_float(h << 16);
                float h1 = __uint_as_float(h & 0xffff0000u);
                uint32_t l = bf2(x1 - h1, x0 - h0);
                sAhi[sr * SW + sw0 + j] = h;
                sAlo[sr * SW + sw0 + j] = l;
            }
        }
        {
            const float* wp = W + (size_t)sr * 128 + k0 + sk;
            float4 v0 = *(const float4*)wp;
            float4 v1 = *(const float4*)(wp + 4);
            float vs[8] = {v0.x, v0.y, v0.z, v0.w, v1.x, v1.y, v1.z, v1.w};
#pragma unroll
            for (int j = 0; j < 4; j++) {
                float x0 = vs[2 * j], x1 = vs[2 * j + 1];
                uint32_t h = bf2(x1, x0);
                float h0 = __uint_as_float(h << 16);
                float h1 = __uint_as_float(h & 0xffff0000u);
                uint32_t l = bf2(x1 - h1, x0 - h0);
                sWhi[sr * SW + sw0 + j] = h;
                sWlo[sr * SW + sw0 + j] = l;
            }
        }
        __syncthreads();

        uint32_t bhi[8][2], blo[8][2];
#pragma unroll
        for (int nf = 0; nf < 8; nf++) {
            int n = wn * 64 + nf * 8 + gid;
            bhi[nf][0] = sWhi[n * SW + tig];
            bhi[nf][1] = sWhi[n * SW + 4 + tig];
            blo[nf][0] = sWlo[n * SW + tig];
            blo[nf][1] = sWlo[n * SW + 4 + tig];
        }
#pragma unroll
        for (int m = 0; m < 2; m++) {
            int r = wm * 32 + m * 16 + gid;
            uint32_t ahi[4], alo[4];
            ahi[0] = sAhi[r * SW + tig];
            ahi[1] = sAhi[(r + 8) * SW + tig];
            ahi[2] = sAhi[r * SW + 4 + tig];
            ahi[3] = sAhi[(r + 8) * SW + 4 + tig];
            alo[0] = sAlo[r * SW + tig];
            alo[1] = sAlo[(r + 8) * SW + tig];
            alo[2] = sAlo[r * SW + 4 + tig];
            alo[3] = sAlo[(r + 8) * SW + 4 + tig];
#pragma unroll
            for (int nf = 0; nf < 8; nf++) {
                mma_bf16(c[m][nf], ahi, bhi[nf]);
                mma_bf16(c[m][nf], ahi, blo[nf]);
                mma_bf16(c[m][nf], alo, bhi[nf]);
            }
        }
        __syncthreads();
    }

#pragma unroll
    for (int nf = 0; nf < 8; nf++) {
        int col = wn * 64 + nf * 8 + 2 * tig;
        float b0 = bias ? bias[col] : 0.0f;
        float b1 = bias ? bias[col + 1] : 0.0f;
#pragma unroll
        for (int m = 0; m < 2; m++) {
            int r = row0 + wm * 32 + m * 16 + gid;
            if (r < nrows)
                *(float2*)(C + (size_t)r * 128 + col) =
                    make_float2(c[m][nf][0] + b0, c[m][nf][1] + b1);
            if (r + 8 < nrows)
                *(float2*)(C + (size_t)(r + 8) * 128 + col) =
                    make_float2(c[m][nf][2] + b0, c[m][nf][3] + b1);
        }
    }
}

__global__ __launch_bounds__(256) void gemm_tc_qkv(const float* __restrict__ A, int nrows,
                                                   const float* __restrict__ Wq,
                                                   const float* __restrict__ Wk,
                                                   const float* __restrict__ Wv) {
    const float* W = (blockIdx.y == 0) ? Wq : (blockIdx.y == 1) ? Wk : Wv;
    float* C       = (blockIdx.y == 0) ? g_q : (blockIdx.y == 1) ? g_k : g_v;
    gemm_bf16_core(A, nrows, W, nullptr, C);
}

__global__ __launch_bounds__(256) void gemm_tc_proj(const float* __restrict__ A, int nrows,
                                                    const float* __restrict__ W,
                                                    const float* __restrict__ bias,
                                                    float* __restrict__ C) {
    gemm_bf16_core(A, nrows, W, bias, C);
}

// ---------------- MLP kernel: LANE-PAIR per edge (R13-proven: 204us) ----------------
#define TSTR 68  // staging row stride (floats)
__global__ __launch_bounds__(128, 5) void mlp_kernel(
    const float* __restrict__ ea,
    const float* __restrict__ W1, const float* __restrict__ W2,
    const float* __restrict__ b2, const float* __restrict__ wb,
    const float* __restrict__ p_sigma, const int* __restrict__ p_log1p,
    const float* __restrict__ p_cscale, int E) {
    __shared__ ull   sW1p2[6 * 36];
    __shared__ ull   sW2p2[32 * 36];
    __shared__ ull   sWbp2[8 * 18];
    __shared__ float sb2[32];
    __shared__ float sTab[4][16 * TSTR];

    int t    = threadIdx.x;
    int wid  = t >> 5;
    int lane = t & 31;
    int q2   = lane & 1;
    int erow = lane >> 1;

    for (int i = t; i < 6 * 32; i += 128) {
        int c = i >> 5, j2 = i & 31;
        sW1p2[c * 36 + (j2 >> 4) * 18 + (j2 & 15)] =
            pk2(W1[(2 * j2) * 38 + c], W1[(2 * j2 + 1) * 38 + c]);
    }
    for (int i = t; i < 32 * 32; i += 128) {
        int r = i >> 5, j2 = i & 31;
        sW2p2[r * 36 + (j2 >> 4) * 18 + (j2 & 15)] =
            pk2(W2[r * 64 + 2 * j2], W2[r * 64 + 2 * j2 + 1]);
    }
    for (int i = t; i < 8 * 16; i += 128) {
        int h = i >> 4, i2 = i & 15;
        sWbp2[h * 18 + i2] = pk2(wb[h * 32 + 2 * i2], wb[h * 32 + 2 * i2 + 1]);
    }
    if (t < 32) sb2[t] = b2[t];
    __syncthreads();

    float sigma  = fmaxf(p_sigma[0], 1e-6f);
    bool  ulog   = (p_log1p[0] != 0);
    float inv_cs = 1.0f / fmaxf(p_cscale[0], 1e-6f);

    int warpsTotal = gridDim.x * 4;
    for (int ebase = (blockIdx.x * 4 + wid) * 16; ebase < E; ebase += warpsTotal * 16) {
        int  e     = ebase + erow;
        bool valid = (e < E);

        float cv[6] = {0, 0, 0, 0, 0, 0};
        int   lr = 0;
        if (valid) {
            const float* a = ea + (size_t)e * 7;
            cv[0] = expf(-a[0] / sigma);
            cv[1] = ulog ? log1pf(fmaxf(a[1], 0.0f)) * inv_cs : a[1] * inv_cs;
            lr    = (int)a[2];
            cv[2] = fminf(fmaxf(a[3], 0.0f), 1.0f);
            cv[3] = fminf(fmaxf(a[4], 0.0f), 1.0f);
            cv[4] = fminf(fmaxf(a[5], 0.0f), 1.0f);
            cv[5] = fminf(fmaxf(a[6], 0.0f), 1.0f);
        }

        __syncwarp();
#pragma unroll
        for (int it2 = 0; it2 < 8; it2++) {
            int r     = it2 * 2 + (lane >> 4);
            int lrr   = __shfl_sync(0xffffffffu, lr, r * 2);
            int chunk = lane & 15;
            if (ebase + r < E) {
                float4 v = *(const float4*)(g_lrtab + (size_t)lrr * 64 + chunk * 4);
                *(float4*)&sTab[wid][r * TSTR + chunk * 4] = v;
            }
        }
        __syncwarp();

        ull cv2[6];
#pragma unroll
        for (int c = 0; c < 6; c++) cv2[c] = pk2(cv[c], cv[c]);

        const float* myrow = &sTab[wid][erow * TSTR + q2 * 32];
        ull h1p[16];
#pragma unroll
        for (int m = 0; m < 8; m++) {
            float4 v = ((const float4*)myrow)[m];
            h1p[2 * m]     = pk2(v.x, v.y);
            h1p[2 * m + 1] = pk2(v.z, v.w);
        }
#pragma unroll
        for (int jj = 0; jj < 16; jj++) {
            ull h = h1p[jj];
#pragma unroll
            for (int c = 0; c < 6; c++)
                h = ffma2(sW1p2[c * 36 + q2 * 18 + jj], cv2[c], h);
            float lo, hi;
            upk2(h, lo, hi);
            h1p[jj] = pk2(fmaxf(lo, 0.0f), fmaxf(hi, 0.0f));
        }

        ull bias2[4] = {0, 0, 0, 0};
#pragma unroll 4
        for (int i2 = 0; i2 < 16; i2++) {
            const ulonglong2* wa  = (const ulonglong2*)&sW2p2[(2 * i2) * 36 + q2 * 18];
            const ulonglong2* wbp = (const ulonglong2*)&sW2p2[(2 * i2 + 1) * 36 + q2 * 18];
            ull accA = 0, accB = 0;
#pragma unroll
            for (int m = 0; m < 8; m++) {
                ulonglong2 wA = wa[m];
                accA = ffma2(h1p[2 * m], wA.x, accA);
                accA = ffma2(h1p[2 * m + 1], wA.y, accA);
                ulonglong2 wB = wbp[m];
                accB = ffma2(h1p[2 * m], wB.x, accB);
                accB = ffma2(h1p[2 * m + 1], wB.y, accB);
            }
            float aL, aH, bL, bH;
            upk2(accA, aL, aH);
            upk2(accB, bL, bH);
            float pA = aL + aH, pB = bL + bH;
            pA += __shfl_xor_sync(0xffffffffu, pA, 1);
            pB += __shfl_xor_sync(0xffffffffu, pB, 1);
            float sA = fmaxf(pA + sb2[2 * i2], 0.0f);
            float sB = fmaxf(pB + sb2[2 * i2 + 1], 0.0f);
            ull sp = pk2(sA, sB);
#pragma unroll
            for (int hh = 0; hh < 4; hh++)
                bias2[hh] = ffma2(sWbp2[(q2 * 4 + hh) * 18 + i2], sp, bias2[hh]);
        }

        if (valid) {
            int pos = g_pos[e];
            float er[4];
#pragma unroll
            for (int hh = 0; hh < 4; hh++) {
                float lo, hi;
                upk2(bias2[hh], lo, hi);
                er[hh] = lo + hi;
            }
            *(float4*)(g_eraw + (size_t)pos * 8 + q2 * 4) =
                make_float4(er[0], er[1], er[2], er[3]);
        }
    }
}

// ---------------- dot kernel: warp per node; e_raw[pos] += (q.k)*dscale; 4x unroll ----
__global__ __launch_bounds__(256) void dot_kernel(const float* __restrict__ p_temp, int n) {
    int lane = threadIdx.x & 31;
    int node = (blockIdx.x * blockDim.x + threadIdx.x) >> 5;
    if (node >= n) return;
    int beg = g_row[node], end = g_row[node + 1];
    if (beg == end) return;

    float tau    = fmaxf(p_temp[0], 1e-6f);
    float dscale = 1.0f / (4.0f * tau);  // sqrt(DK)=4

    float4 qv = *(const float4*)(g_q + (size_t)node * 128 + lane * 4);

    bool storer = ((lane & 3) == 0);
    int  hidx   = lane >> 2;

    int i = beg;
    for (; i + 4 <= end; i += 4) {
        int s0 = g_csr_src[i];
        int s1 = g_csr_src[i + 1];
        int s2 = g_csr_src[i + 2];
        int s3 = g_csr_src[i + 3];
        float4 k0 = *(const float4*)(g_k + (size_t)s0 * 128 + lane * 4);
        float4 k1 = *(const float4*)(g_k + (size_t)s1 * 128 + lane * 4);
        float4 k2 = *(const float4*)(g_k + (size_t)s2 * 128 + lane * 4);
        float4 k3 = *(const float4*)(g_k + (size_t)s3 * 128 + lane * 4);
        float p0 = qv.x * k0.x + qv.y * k0.y + qv.z * k0.z + qv.w * k0.w;
        float p1 = qv.x * k1.x + qv.y * k1.y + qv.z * k1.z + qv.w * k1.w;
        float p2 = qv.x * k2.x + qv.y * k2.y + qv.z * k2.z + qv.w * k2.w;
        float p3 = qv.x * k3.x + qv.y * k3.y + qv.z * k3.z + qv.w * k3.w;
        p0 += __shfl_xor_sync(0xffffffffu, p0, 1);
        p1 += __shfl_xor_sync(0xffffffffu, p1, 1);
        p2 += __shfl_xor_sync(0xffffffffu, p2, 1);
        p3 += __shfl_xor_sync(0xffffffffu, p3, 1);
        p0 += __shfl_xor_sync(0xffffffffu, p0, 2);
        p1 += __shfl_xor_sync(0xffffffffu, p1, 2);
        p2 += __shfl_xor_sync(0xffffffffu, p2, 2);
        p3 += __shfl_xor_sync(0xffffffffu, p3, 2);
        if (storer) {
            float* d0 = g_eraw + (size_t)(i + 0) * 8 + hidx;
            float* d1 = g_eraw + (size_t)(i + 1) * 8 + hidx;
            float* d2 = g_eraw + (size_t)(i + 2) * 8 + hidx;
            float* d3 = g_eraw + (size_t)(i + 3) * 8 + hidx;
            *d0 = *d0 + p0 * dscale;
            *d1 = *d1 + p1 * dscale;
            *d2 = *d2 + p2 * dscale;
            *d3 = *d3 + p3 * dscale;
        }
    }
    for (; i < end; i++) {
        int src = g_csr_src[i];
        float4 kv = *(const float4*)(g_k + (size_t)src * 128 + lane * 4);
        float p = qv.x * kv.x + qv.y * kv.y + qv.z * kv.z + qv.w * kv.w;
        p += __shfl_xor_sync(0xffffffffu, p, 1);
        p += __shfl_xor_sync(0xffffffffu, p, 2);
        if (storer) {
            float* dst = g_eraw + (size_t)i * 8 + hidx;
            *dst = *dst + p * dscale;
        }
    }
}

// ---------------- node_attn: stats + tanh + e_out scatter + softmax + alpha.v ----------------
__global__ __launch_bounds__(256) void node_attn(float* __restrict__ e_out, int n) {
    int lane = threadIdx.x & 31;
    int node = (blockIdx.x * blockDim.x + threadIdx.x) >> 5;
    if (node >= n) return;
    int beg = g_row[node], end = g_row[node + 1];

    if (beg == end) {
        *(float4*)(g_outpre + (size_t)node * 128 + lane * 4) =
            make_float4(0.f, 0.f, 0.f, 0.f);
        return;
    }

    int head = lane & 7, sub = lane >> 3;

    float s1 = 0.0f, s2 = 0.0f;
    for (int i = beg + sub; i < end; i += 4) {
        float v = g_eraw[(size_t)i * 8 + head];
        s1 += v;
        s2 += v * v;
    }
    s1 += __shfl_xor_sync(0xffffffffu, s1, 8);
    s1 += __shfl_xor_sync(0xffffffffu, s1, 16);
    s2 += __shfl_xor_sync(0xffffffffu, s2, 8);
    s2 += __shfl_xor_sync(0xffffffffu, s2, 16);
    float c    = fmaxf((float)(end - beg), 1.0f);
    float m    = s1 / c;
    float var  = fmaxf(s2 / c - m * m, 0.0f);
    float rstd = 1.0f / (sqrtf(var + 1e-6f) + 1e-6f);

    float dn = 0.0f;
    for (int i = beg + sub; i < end; i += 4) {
        float v  = g_eraw[(size_t)i * 8 + head];
        float te = tanhf((v - m) * rstd);
        g_etan[(size_t)i * 8 + head] = te;
        int eid = g_csr_eid[i];
        e_out[(size_t)eid * 8 + head] = te;
        dn += expf(te);
    }
    dn += __shfl_xor_sync(0xffffffffu, dn, 8);
    dn += __shfl_xor_sync(0xffffffffu, dn, 16);
    float inv  = 1.0f / (dn + 1e-12f);
    float invh = __shfl_sync(0xffffffffu, inv, lane >> 2);
    int   hidx = lane >> 2;

    float4 acc = make_float4(0.f, 0.f, 0.f, 0.f);
    int i = beg;
    for (; i + 2 <= end; i += 2) {
        int s0  = g_csr_src[i];
        int s1i = g_csr_src[i + 1];
        float t0 = g_etan[(size_t)(i + 0) * 8 + hidx];
        float t1 = g_etan[(size_t)(i + 1) * 8 + hidx];
        float4 v0 = *(const float4*)(g_v + (size_t)s0 * 128 + lane * 4);
        float4 v1 = *(const float4*)(g_v + (size_t)s1i * 128 + lane * 4);
        float a0 = expf(t0) * invh;
        float a1 = expf(t1) * invh;
        acc.x += a0 * v0.x + a1 * v1.x;
        acc.y += a0 * v0.y + a1 * v1.y;
        acc.z += a0 * v0.z + a1 * v1.z;
        acc.w += a0 * v0.w + a1 * v1.w;
    }
    for (; i < end; i++) {
        int src = g_csr_src[i];
        float te    = g_etan[(size_t)i * 8 + hidx];
        float alpha = expf(te) * invh;
        float4 vv = *(const float4*)(g_v + (size_t)src * 128 + lane * 4);
        acc.x += alpha * vv.x;
        acc.y += alpha * vv.y;
        acc.z += alpha * vv.z;
        acc.w += alpha * vv.w;
    }
    *(float4*)(g_outpre + (size_t)node * 128 + lane * 4) = acc;
}

// ---------------- launch ----------------
extern "C" void kernel_launch(void* const* d_in, const int* in_sizes, int n_in,
                              void* d_out, int out_size) {
    const float* x   = (const float*)d_in[0];
    const int*   ei  = (const int*)d_in[1];
    const float* ea  = (const float*)d_in[2];
    const float* Wq  = (const float*)d_in[3];
    const float* Wk  = (const float*)d_in[4];
    const float* Wv  = (const float*)d_in[5];
    const float* lre = (const float*)d_in[6];
    const float* W1  = (const float*)d_in[7];
    const float* b1  = (const float*)d_in[8];
    const float* W2  = (const float*)d_in[9];
    const float* b2  = (const float*)d_in[10];
    const float* wb  = (const float*)d_in[11];
    const float* Wp  = (const float*)d_in[12];
    const float* bp  = (const float*)d_in[13];
    const float* p_sigma  = (const float*)d_in[14];
    const int*   p_log1p  = (const int*)d_in[15];
    const float* p_cscale = (const float*)d_in[16];
    const float* p_temp   = (const float*)d_in[17];

    int n = in_sizes[0] / 128;
    int E = in_sizes[1] / 2;

    float* out   = (float*)d_out;
    float* e_out = out + (size_t)n * 128;  // output layout: (out[N,128], e[E,8])

    void* pcnt;
    void* pop;
    cudaGetSymbolAddress(&pcnt, g_cnt);
    cudaGetSymbolAddress(&pop, g_outpre);

    // launch order matters for ncu's fixed capture slot (5th launch incl. memset)
    cudaMemsetAsync(pcnt, 0, (size_t)n * sizeof(int));                       // 1
    lrtab_hist<<<LRTAB_BLOCKS + (E + 511) / 512, 512>>>(W1, b1, lre, ei, E); // 2
    scan_kernel<<<1, 1024>>>(n);                                             // 3
    scatter_kernel<<<(E + 511) / 512, 512>>>(ei, E);                         // 4
    mlp_kernel<<<2048, 128>>>(ea, W1, W2, b2, wb, p_sigma, p_log1p,
                              p_cscale, E);                                  // 5 <- captured

    dim3 gq((n + 127) / 128, 3);
    gemm_tc_qkv<<<gq, 256>>>(x, n, Wq, Wk, Wv);

    dot_kernel<<<(n * 32 + 255) / 256, 256>>>(p_temp, n);

    node_attn<<<(n * 32 + 255) / 256, 256>>>(e_out, n);

    gemm_tc_proj<<<(n + 127) / 128, 256>>>((const float*)pop, n, Wp, bp, out);
}